// round 1
// baseline (speedup 1.0000x reference)
#include <cuda_runtime.h>

// UniSAGE model is fully linear => compute the scalar output by pulling the
// final averaging functionals backwards through the network. Only scalar
// per-vertex / per-edge vectors are ever materialized.

#define NV  100000
#define NE  200000
#define NNZt 800000
#define DIN 14
#define HID 128

// -------- device scratch (allocation-free) --------
__device__ float g_deg[NV];
__device__ float g_p  [NV];   // raw (P^T applied) part of p
__device__ float g_p2 [NV];   // raw part of p2
__device__ float g_r2 [NV];   // raw part of r2
__device__ float g_zp [NE];
__device__ float g_zr [NE];
__device__ float g_zp2[NE];
__device__ float g_acc[33];   // [0..13]=p2^T X, [14..27]=r2^T X, 28=sum p, 29=sum p2, 30=sum r2

__global__ void k_zero() {
    int i = blockIdx.x * blockDim.x + threadIdx.x;
    if (i < NV) { g_deg[i] = 0.f; g_p[i] = 0.f; g_p2[i] = 0.f; g_r2[i] = 0.f; }
    if (i < NE) { g_zp[i] = 0.f; g_zr[i] = 0.f; g_zp2[i] = 0.f; }
    if (i < 33) g_acc[i] = 0.f;
}

__global__ void k_deg(const int* __restrict__ rows) {
    int i = blockIdx.x * blockDim.x + threadIdx.x;
    if (i * 4 < NNZt) {
        int4 r = ((const int4*)rows)[i];
        atomicAdd(&g_deg[r.x], 1.f);
        atomicAdd(&g_deg[r.y], 1.f);
        atomicAdd(&g_deg[r.z], 1.f);
        atomicAdd(&g_deg[r.w], 1.f);
    }
}

// scatter vertex->edge for both functionals:
//   z_p[e] += (1/NV) / deg[v]          (w_p = 1/NV constant)
//   z_r[e] += (deg[v]/NE) / deg[v] = 1/NE
__global__ void k_scat1(const int* __restrict__ rows, const int* __restrict__ cols) {
    int i = blockIdx.x * blockDim.x + threadIdx.x;
    if (i * 4 < NNZt) {
        int4 r = ((const int4*)rows)[i];
        int4 c = ((const int4*)cols)[i];
        const float wp = 1.0f / (float)NV;
        const float wr = 1.0f / (float)NE;
        atomicAdd(&g_zp[c.x], wp / g_deg[r.x]);
        atomicAdd(&g_zp[c.y], wp / g_deg[r.y]);
        atomicAdd(&g_zp[c.z], wp / g_deg[r.z]);
        atomicAdd(&g_zp[c.w], wp / g_deg[r.w]);
        atomicAdd(&g_zr[c.x], wr);
        atomicAdd(&g_zr[c.y], wr);
        atomicAdd(&g_zr[c.z], wr);
        atomicAdd(&g_zr[c.w], wr);
    }
}

// gather edge->vertex: p_raw[v] += z_p[e], r2_raw[v] += z_r[e]
__global__ void k_gath1(const int* __restrict__ rows, const int* __restrict__ cols) {
    int i = blockIdx.x * blockDim.x + threadIdx.x;
    if (i * 4 < NNZt) {
        int4 r = ((const int4*)rows)[i];
        int4 c = ((const int4*)cols)[i];
        atomicAdd(&g_p[r.x], g_zp[c.x]);
        atomicAdd(&g_p[r.y], g_zp[c.y]);
        atomicAdd(&g_p[r.z], g_zp[c.z]);
        atomicAdd(&g_p[r.w], g_zp[c.w]);
        atomicAdd(&g_r2[r.x], g_zr[c.x]);
        atomicAdd(&g_r2[r.y], g_zr[c.y]);
        atomicAdd(&g_r2[r.z], g_zr[c.z]);
        atomicAdd(&g_r2[r.w], g_zr[c.w]);
    }
}

// second application for p2: uses full p = p_raw + 1/NV (identity term folded in)
__global__ void k_scat2(const int* __restrict__ rows, const int* __restrict__ cols) {
    int i = blockIdx.x * blockDim.x + threadIdx.x;
    if (i * 4 < NNZt) {
        int4 r = ((const int4*)rows)[i];
        int4 c = ((const int4*)cols)[i];
        const float wp = 1.0f / (float)NV;
        atomicAdd(&g_zp2[c.x], (g_p[r.x] + wp) / g_deg[r.x]);
        atomicAdd(&g_zp2[c.y], (g_p[r.y] + wp) / g_deg[r.y]);
        atomicAdd(&g_zp2[c.z], (g_p[r.z] + wp) / g_deg[r.z]);
        atomicAdd(&g_zp2[c.w], (g_p[r.w] + wp) / g_deg[r.w]);
    }
}

__global__ void k_gath2(const int* __restrict__ rows, const int* __restrict__ cols) {
    int i = blockIdx.x * blockDim.x + threadIdx.x;
    if (i * 4 < NNZt) {
        int4 r = ((const int4*)rows)[i];
        int4 c = ((const int4*)cols)[i];
        atomicAdd(&g_p2[r.x], g_zp2[c.x]);
        atomicAdd(&g_p2[r.y], g_zp2[c.y]);
        atomicAdd(&g_p2[r.z], g_zp2[c.z]);
        atomicAdd(&g_p2[r.w], g_zp2[c.w]);
    }
}

// per-vertex reduction: sums of p, p2, r2 and weighted column sums of x_0
__global__ void k_reduce(const float* __restrict__ x0) {
    int v = blockIdx.x * blockDim.x + threadIdx.x;
    float vals[31];
#pragma unroll
    for (int k = 0; k < 31; k++) vals[k] = 0.f;
    if (v < NV) {
        float pv  = g_p[v] + 1.0f / (float)NV;       // full p (identity folded)
        float p2v = g_p2[v] + pv;                    // p2 = p2_raw + p
        float r2v = g_r2[v] + g_deg[v] * (1.0f / (float)NE);  // r2 = r2_raw + r
        const float* xr = x0 + (long long)v * DIN;
#pragma unroll
        for (int j = 0; j < DIN; j++) {
            float x = xr[j];
            vals[j]       = p2v * x;
            vals[14 + j]  = r2v * x;
        }
        vals[28] = pv; vals[29] = p2v; vals[30] = r2v;
    }
    // warp reduce all 31
#pragma unroll
    for (int k = 0; k < 31; k++) {
#pragma unroll
        for (int off = 16; off > 0; off >>= 1)
            vals[k] += __shfl_down_sync(0xffffffffu, vals[k], off);
    }
    __shared__ float sh[8 * 31];
    int warp = threadIdx.x >> 5, lane = threadIdx.x & 31;
    if (lane == 0) {
#pragma unroll
        for (int k = 0; k < 31; k++) sh[warp * 31 + k] = vals[k];
    }
    __syncthreads();
    if (threadIdx.x < 31) {
        float s = 0.f;
#pragma unroll
        for (int w = 0; w < 8; w++) s += sh[w * 31 + threadIdx.x];
        atomicAdd(&g_acc[threadIdx.x], s);
    }
}

// tiny GEMV chain: (1x14) -> (1x128) -> (1x128) -> (1x128) -> scalar, both branches
__global__ void k_final(const float* __restrict__ W0, const float* __restrict__ b0,
                        const float* __restrict__ Wl0, const float* __restrict__ bl0,
                        const float* __restrict__ Wl1, const float* __restrict__ bl1,
                        const float* __restrict__ Wo0, const float* __restrict__ bo0,
                        const float* __restrict__ Wo1, const float* __restrict__ bo1,
                        float* __restrict__ out) {
    __shared__ float a0[HID], c0[HID], a1[HID], c1[HID], red[HID];
    int h = threadIdx.x;
    float sp  = g_acc[28];
    float sp2 = g_acc[29];
    float sr2 = g_acc[30];
    float sr  = (float)NNZt / (float)NE;   // 1^T (deg/NE) = NNZ/NE exactly

    float sa = 0.f, sc = 0.f;
#pragma unroll
    for (int j = 0; j < DIN; j++) {
        float w = W0[j * HID + h];
        sa += g_acc[j] * w;
        sc += g_acc[14 + j] * w;
    }
    a0[h] = sa + sp2 * b0[h];
    c0[h] = sc + sr2 * b0[h];
    __syncthreads();

    sa = 0.f; sc = 0.f;
    for (int m = 0; m < HID; m++) {
        float w = Wl0[m * HID + h];
        sa += a0[m] * w;
        sc += c0[m] * w;
    }
    a1[h] = sa + sp2 * bl0[h];
    c1[h] = sc + sr2 * bl0[h];
    __syncthreads();

    sa = 0.f; sc = 0.f;
    for (int m = 0; m < HID; m++) {
        float w = Wl1[m * HID + h];
        sa += a1[m] * w;
        sc += c1[m] * w;
    }
    float a2h = sa + sp * bl1[h];   // p^T h2
    float c2h = sc + sr * bl1[h];   // r^T h2
    red[h] = a2h * Wo0[h] + c2h * Wo1[h];
    __syncthreads();

    for (int s = HID / 2; s > 0; s >>= 1) {
        if (h < s) red[h] += red[h + s];
        __syncthreads();
    }
    if (h == 0) out[0] = red[0] + bo0[0] + bo1[0];
}

extern "C" void kernel_launch(void* const* d_in, const int* in_sizes, int n_in,
                              void* d_out, int out_size) {
    const float* x_0  = (const float*)d_in[0];
    // d_in[1] = x_1 (unused: its projection is overwritten in the reference)
    const int*   rows = (const int*)d_in[2];
    const int*   cols = (const int*)d_in[3];
    const float* W0   = (const float*)d_in[4];
    const float* b0   = (const float*)d_in[5];
    // d_in[6], d_in[7] = W1_in, b1_in (unused)
    const float* Wl0  = (const float*)d_in[8];
    const float* bl0  = (const float*)d_in[9];
    const float* Wl1  = (const float*)d_in[10];
    const float* bl1  = (const float*)d_in[11];
    const float* Wo0  = (const float*)d_in[12];
    const float* bo0  = (const float*)d_in[13];
    const float* Wo1  = (const float*)d_in[14];
    const float* bo1  = (const float*)d_in[15];
    float* out = (float*)d_out;

    const int T = 256;
    const int gZero = (NE + T - 1) / T;          // NE >= NV, covers all
    const int gNnz4 = (NNZt / 4 + T - 1) / T;
    const int gNV   = (NV + T - 1) / T;

    k_zero <<<gZero, T>>>();
    k_deg  <<<gNnz4, T>>>(rows);
    k_scat1<<<gNnz4, T>>>(rows, cols);
    k_gath1<<<gNnz4, T>>>(rows, cols);
    k_scat2<<<gNnz4, T>>>(rows, cols);
    k_gath2<<<gNnz4, T>>>(rows, cols);
    k_reduce<<<gNV, T>>>(x_0);
    k_final<<<1, HID>>>(W0, b0, Wl0, bl0, Wl1, bl1, Wo0, bo0, Wo1, bo1, out);
}

// round 2
// speedup vs baseline: 1.2005x; 1.2005x over previous
#include <cuda_runtime.h>

// UniSAGE is fully linear => pull the final averaging functionals backwards.
// Only scalar/float2 per-vertex & per-edge vectors are materialized.
// R2: pack paired scalars into float2, use red.global.add.v2.f32, fold edge
// degree counting into scat1, hoist divisions out of NNZ passes.

#define NV   100000
#define NE   200000
#define NNZt 800000
#define DIN  14
#define HID  128
#define WP   (1.0f / (float)NV)
#define WR   (1.0f / (float)NE)

// -------- device scratch (allocation-free) --------
__device__ float  g_deg[NV];
__device__ float2 g_pv2[NV];    // {p_raw, r2_raw}
__device__ float  g_q  [NV];    // (p_raw + 1/NV) / deg
__device__ float  g_p2 [NV];    // p2_raw
__device__ float2 g_ze [NE];    // {zp, edeg}
__device__ float  g_zp2[NE];
__device__ float  g_acc[32];    // [0..13]=p2^T X, [14..27]=r2^T X, 28=Σp, 29=Σp2, 30=Σr2

__device__ __forceinline__ void red2(float2* a, float x, float y) {
    asm volatile("red.global.add.v2.f32 [%0], {%1,%2};" :: "l"(a), "f"(x), "f"(y) : "memory");
}

__global__ void k_zero() {
    int i = blockIdx.x * blockDim.x + threadIdx.x;
    if (i < NV) {
        g_deg[i] = 0.f; g_p2[i] = 0.f;
        g_pv2[i] = make_float2(0.f, 0.f);
    }
    if (i < NE) {
        g_ze[i] = make_float2(0.f, 0.f);
        g_zp2[i] = 0.f;
    }
    if (i < 32) g_acc[i] = 0.f;
}

__global__ void k_deg(const int* __restrict__ rows) {
    int i = blockIdx.x * blockDim.x + threadIdx.x;
    if (i * 4 < NNZt) {
        int4 r = ((const int4*)rows)[i];
        atomicAdd(&g_deg[r.x], 1.f);
        atomicAdd(&g_deg[r.y], 1.f);
        atomicAdd(&g_deg[r.z], 1.f);
        atomicAdd(&g_deg[r.w], 1.f);
    }
}

// ze[e] += { (1/NV)/deg[v], 1 }   (zp scatter + edge-degree count fused)
__global__ void k_scat1(const int* __restrict__ rows, const int* __restrict__ cols) {
    int i = blockIdx.x * blockDim.x + threadIdx.x;
    if (i * 4 < NNZt) {
        int4 r = ((const int4*)rows)[i];
        int4 c = ((const int4*)cols)[i];
        float dx = g_deg[r.x], dy = g_deg[r.y], dz = g_deg[r.z], dw = g_deg[r.w];
        red2(&g_ze[c.x], __fdividef(WP, dx), 1.f);
        red2(&g_ze[c.y], __fdividef(WP, dy), 1.f);
        red2(&g_ze[c.z], __fdividef(WP, dz), 1.f);
        red2(&g_ze[c.w], __fdividef(WP, dw), 1.f);
    }
}

// pv2[v] += { zp[e], edeg[e]/NE }
__global__ void k_gath1(const int* __restrict__ rows, const int* __restrict__ cols) {
    int i = blockIdx.x * blockDim.x + threadIdx.x;
    if (i * 4 < NNZt) {
        int4 r = ((const int4*)rows)[i];
        int4 c = ((const int4*)cols)[i];
        float2 zx = g_ze[c.x], zy = g_ze[c.y], zz = g_ze[c.z], zw = g_ze[c.w];
        red2(&g_pv2[r.x], zx.x, zx.y * WR);
        red2(&g_pv2[r.y], zy.x, zy.y * WR);
        red2(&g_pv2[r.z], zz.x, zz.y * WR);
        red2(&g_pv2[r.w], zw.x, zw.y * WR);
    }
}

// q[v] = (p_raw[v] + 1/NV) / deg[v]   (unused when deg==0, keep finite)
__global__ void k_prep(){
    int v = blockIdx.x * blockDim.x + threadIdx.x;
    if (v < NV) {
        float d = g_deg[v];
        g_q[v] = __fdividef(g_pv2[v].x + WP, d > 0.f ? d : 1.f);
    }
}

__global__ void k_scat2(const int* __restrict__ rows, const int* __restrict__ cols) {
    int i = blockIdx.x * blockDim.x + threadIdx.x;
    if (i * 4 < NNZt) {
        int4 r = ((const int4*)rows)[i];
        int4 c = ((const int4*)cols)[i];
        atomicAdd(&g_zp2[c.x], g_q[r.x]);
        atomicAdd(&g_zp2[c.y], g_q[r.y]);
        atomicAdd(&g_zp2[c.z], g_q[r.z]);
        atomicAdd(&g_zp2[c.w], g_q[r.w]);
    }
}

__global__ void k_gath2(const int* __restrict__ rows, const int* __restrict__ cols) {
    int i = blockIdx.x * blockDim.x + threadIdx.x;
    if (i * 4 < NNZt) {
        int4 r = ((const int4*)rows)[i];
        int4 c = ((const int4*)cols)[i];
        atomicAdd(&g_p2[r.x], g_zp2[c.x]);
        atomicAdd(&g_p2[r.y], g_zp2[c.y]);
        atomicAdd(&g_p2[r.z], g_zp2[c.z]);
        atomicAdd(&g_p2[r.w], g_zp2[c.w]);
    }
}

// per-vertex reduction: Σp, Σp2, Σr2, p2^T X, r2^T X
__global__ void k_reduce(const float* __restrict__ x0) {
    int v = blockIdx.x * blockDim.x + threadIdx.x;
    float vals[31];
#pragma unroll
    for (int k = 0; k < 31; k++) vals[k] = 0.f;
    if (v < NV) {
        float2 pr = g_pv2[v];
        float pv  = pr.x + WP;                    // full p (identity folded)
        float p2v = g_p2[v] + pv;                 // p2 = p2_raw + p
        float r2v = pr.y + g_deg[v] * WR;         // r2 = r2_raw + r
        const float* xr = x0 + (long long)v * DIN;
#pragma unroll
        for (int j = 0; j < DIN; j++) {
            float x = xr[j];
            vals[j]      = p2v * x;
            vals[14 + j] = r2v * x;
        }
        vals[28] = pv; vals[29] = p2v; vals[30] = r2v;
    }
#pragma unroll
    for (int k = 0; k < 31; k++) {
#pragma unroll
        for (int off = 16; off > 0; off >>= 1)
            vals[k] += __shfl_down_sync(0xffffffffu, vals[k], off);
    }
    __shared__ float sh[8 * 31];
    int warp = threadIdx.x >> 5, lane = threadIdx.x & 31;
    if (lane == 0) {
#pragma unroll
        for (int k = 0; k < 31; k++) sh[warp * 31 + k] = vals[k];
    }
    __syncthreads();
    if (threadIdx.x < 31) {
        float s = 0.f;
#pragma unroll
        for (int w = 0; w < 8; w++) s += sh[w * 31 + threadIdx.x];
        atomicAdd(&g_acc[threadIdx.x], s);
    }
}

// tiny GEMV chain: (1x14) -> (1x128) -> (1x128) -> (1x128) -> scalar, both branches
__global__ void k_final(const float* __restrict__ W0, const float* __restrict__ b0,
                        const float* __restrict__ Wl0, const float* __restrict__ bl0,
                        const float* __restrict__ Wl1, const float* __restrict__ bl1,
                        const float* __restrict__ Wo0, const float* __restrict__ bo0,
                        const float* __restrict__ Wo1, const float* __restrict__ bo1,
                        float* __restrict__ out) {
    __shared__ float a0[HID], c0[HID], a1[HID], c1[HID], red[HID];
    int h = threadIdx.x;
    float sp  = g_acc[28];
    float sp2 = g_acc[29];
    float sr2 = g_acc[30];
    float sr  = (float)NNZt / (float)NE;   // 1^T (deg/NE) = NNZ/NE exactly

    float sa = 0.f, sc = 0.f;
#pragma unroll
    for (int j = 0; j < DIN; j++) {
        float w = W0[j * HID + h];
        sa += g_acc[j] * w;
        sc += g_acc[14 + j] * w;
    }
    a0[h] = sa + sp2 * b0[h];
    c0[h] = sc + sr2 * b0[h];
    __syncthreads();

    sa = 0.f; sc = 0.f;
    for (int m = 0; m < HID; m++) {
        float w = Wl0[m * HID + h];
        sa += a0[m] * w;
        sc += c0[m] * w;
    }
    a1[h] = sa + sp2 * bl0[h];
    c1[h] = sc + sr2 * bl0[h];
    __syncthreads();

    sa = 0.f; sc = 0.f;
    for (int m = 0; m < HID; m++) {
        float w = Wl1[m * HID + h];
        sa += a1[m] * w;
        sc += c1[m] * w;
    }
    float a2h = sa + sp * bl1[h];   // p^T h2
    float c2h = sc + sr * bl1[h];   // r^T h2
    red[h] = a2h * Wo0[h] + c2h * Wo1[h];
    __syncthreads();

    for (int s = HID / 2; s > 0; s >>= 1) {
        if (h < s) red[h] += red[h + s];
        __syncthreads();
    }
    if (h == 0) out[0] = red[0] + bo0[0] + bo1[0];
}

extern "C" void kernel_launch(void* const* d_in, const int* in_sizes, int n_in,
                              void* d_out, int out_size) {
    const float* x_0  = (const float*)d_in[0];
    const int*   rows = (const int*)d_in[2];
    const int*   cols = (const int*)d_in[3];
    const float* W0   = (const float*)d_in[4];
    const float* b0   = (const float*)d_in[5];
    const float* Wl0  = (const float*)d_in[8];
    const float* bl0  = (const float*)d_in[9];
    const float* Wl1  = (const float*)d_in[10];
    const float* bl1  = (const float*)d_in[11];
    const float* Wo0  = (const float*)d_in[12];
    const float* bo0  = (const float*)d_in[13];
    const float* Wo1  = (const float*)d_in[14];
    const float* bo1  = (const float*)d_in[15];
    float* out = (float*)d_out;

    const int T = 256;
    const int gZero = (NE + T - 1) / T;
    const int gNnz4 = (NNZt / 4 + T - 1) / T;
    const int gNV   = (NV + T - 1) / T;

    k_zero <<<gZero, T>>>();
    k_deg  <<<gNnz4, T>>>(rows);
    k_scat1<<<gNnz4, T>>>(rows, cols);
    k_gath1<<<gNnz4, T>>>(rows, cols);
    k_prep <<<gNV,   T>>>();
    k_scat2<<<gNnz4, T>>>(rows, cols);
    k_gath2<<<gNnz4, T>>>(rows, cols);
    k_reduce<<<gNV,  T>>>(x_0);
    k_final<<<1, HID>>>(W0, b0, Wl0, bl0, Wl1, bl1, Wo0, bo0, Wo1, bo1, out);
}